// round 8
// baseline (speedup 1.0000x reference)
#include <cuda_runtime.h>
#include <cuda_bf16.h>
#include <math.h>
#include <stdint.h>

#define Nn   4
#define CIN  1024
#define CB   256
#define Hh   56
#define Ww   56
#define HW   3136
#define KT   9
#define KD   (CB * KT)   // 2304

// Scratch (device globals: allocation-free rule)
__device__ float g_r  [Nn * CB * HW];     // conv1 output (relu), NCHW
__device__ float g_rt [Nn * HW * CB];     // conv1 output, NHWC (for gather)
__device__ float g_off[Nn * 2 * KT * HW]; // offset conv output
__device__ float g_r2 [Nn * CB * HW];     // deform conv output (relu)
__device__ __nv_bfloat16 g_w2h[CB * KD];  // w2 split hi, [o][tap*256+c]
__device__ __nv_bfloat16 g_w2l[CB * KD];  // w2 split lo

// ---------------------------------------------------------------------------
// helpers
// ---------------------------------------------------------------------------
__device__ __forceinline__ void split2(float x, float y, uint32_t& hi, uint32_t& lo) {
    __nv_bfloat16 xh = __float2bfloat16(x);
    __nv_bfloat16 yh = __float2bfloat16(y);
    __nv_bfloat16 xl = __float2bfloat16(x - __bfloat162float(xh));
    __nv_bfloat16 yl = __float2bfloat16(y - __bfloat162float(yh));
    hi = ((uint32_t)__bfloat16_as_ushort(yh) << 16) | __bfloat16_as_ushort(xh);
    lo = ((uint32_t)__bfloat16_as_ushort(yl) << 16) | __bfloat16_as_ushort(xl);
}
__device__ __forceinline__ void split8(const float4& a, const float4& b,
                                       uint4& hi, uint4& lo) {
    split2(a.x, a.y, hi.x, lo.x);
    split2(a.z, a.w, hi.y, lo.y);
    split2(b.x, b.y, hi.z, lo.z);
    split2(b.z, b.w, hi.w, lo.w);
}

__device__ __forceinline__ void mma16816(float* c, const uint32_t* a, const uint32_t* b) {
    asm volatile(
        "mma.sync.aligned.m16n8k16.row.col.f32.bf16.bf16.f32 "
        "{%0,%1,%2,%3}, {%4,%5,%6,%7}, {%8,%9}, {%0,%1,%2,%3};"
        : "+f"(c[0]), "+f"(c[1]), "+f"(c[2]), "+f"(c[3])
        : "r"(a[0]), "r"(a[1]), "r"(a[2]), "r"(a[3]), "r"(b[0]), "r"(b[1]));
}

__device__ __forceinline__ void ldsm_x4(uint32_t* r, uint32_t addr) {
    asm volatile("ldmatrix.sync.aligned.m8n8.x4.shared.b16 {%0,%1,%2,%3}, [%4];"
                 : "=r"(r[0]), "=r"(r[1]), "=r"(r[2]), "=r"(r[3]) : "r"(addr));
}
template <int P>
__device__ __forceinline__ uint32_t a_addr(const __nv_bfloat16 (*S)[P], int mb, int ks, int ln) {
    int row = mb + (ln & 7) + ((ln >> 3) & 1) * 8;
    int col = ks + (ln >> 4) * 8;
    return (uint32_t)__cvta_generic_to_shared(&S[row][col]);
}
// B ldsm_x4: loads TWO n-frags (16 rows) x k16; frags: nf0={r0,r1}, nf1={r2,r3}
template <int P>
__device__ __forceinline__ uint32_t b_addr4(const __nv_bfloat16 (*S)[P], int nb, int ks, int ln) {
    int row = nb + ((ln >> 4) << 3) + (ln & 7);
    int col = ks + ((ln >> 3) & 1) * 8;
    return (uint32_t)__cvta_generic_to_shared(&S[row][col]);
}
__device__ __forceinline__ void cp16(uint32_t saddr, const void* g) {
    asm volatile("cp.async.ca.shared.global [%0], [%1], 16;"
                 :: "r"(saddr), "l"(g) : "memory");
}
#define CP_COMMIT() asm volatile("cp.async.commit_group;" ::: "memory")
#define CP_WAIT0()  asm volatile("cp.async.wait_group 0;" ::: "memory")

// ---------------------------------------------------------------------------
// w2 (o,c,kh,kw) fp32 -> bf16 hi/lo at [o][tap*256+c]
// ---------------------------------------------------------------------------
__global__ void prep_w2_kernel(const float* __restrict__ w2) {
    int i = blockIdx.x * 256 + threadIdx.x;
    if (i < CB * KD) {
        int o = i / KD;
        int k = i % KD;
        int tap = k >> 8;
        int c   = k & 255;
        float v = w2[(o * CB + c) * KT + tap];
        __nv_bfloat16 h = __float2bfloat16(v);
        g_w2h[i] = h;
        g_w2l[i] = __float2bfloat16(v - __bfloat162float(h));
    }
}

// ---------------------------------------------------------------------------
// NCHW -> NHWC tiled transpose of g_r into g_rt
// ---------------------------------------------------------------------------
__global__ void nchw2nhwc_kernel() {
    __shared__ float t[32][33];
    const int n  = blockIdx.z;
    const int p0 = blockIdx.x * 32;
    const int c0 = blockIdx.y * 32;
    const int tx = threadIdx.x;      // 0..31
    const int ty = threadIdx.y;      // 0..7
#pragma unroll
    for (int i = 0; i < 4; ++i) {
        int c = c0 + ty + i * 8;
        t[ty + i * 8][tx] = g_r[((size_t)n * CB + c) * HW + p0 + tx];
    }
    __syncthreads();
#pragma unroll
    for (int i = 0; i < 4; ++i) {
        int p = p0 + ty + i * 8;
        g_rt[((size_t)n * HW + p) * CB + c0 + tx] = t[tx][ty + i * 8];
    }
}

// ===========================================================================
// Tensor-core (HMMA) GEMM for the 1x1 convs. B via ldsm_x4 (2 nf per ldsm).
// ===========================================================================
#define BKP 40

__global__ __launch_bounds__(256) void gemm_tc_kernel(
        const float* __restrict__ A, const float* __restrict__ Bx,
        const float* __restrict__ bias, const float* __restrict__ resid,
        float* __restrict__ C, int M, int Kd) {
    __shared__ __nv_bfloat16 As_hi[128][BKP];
    __shared__ __nv_bfloat16 As_lo[128][BKP];
    __shared__ __nv_bfloat16 Bs_hi[64][BKP];
    __shared__ __nv_bfloat16 Bs_lo[64][BKP];

    const int n  = blockIdx.z;
    const int m0 = blockIdx.y * 128;
    const int p0 = blockIdx.x * 64;
    const int tid = threadIdx.x;
    const int wid = tid >> 5;
    const int lid = tid & 31;
    const int q = lid >> 2;
    const int r = lid & 3;
    const int warp_m = wid >> 2;
    const int warp_n = wid & 3;
    const float* Bn = Bx + (size_t)n * Kd * HW;

    const int a_row0 = tid >> 2;
    const int a_kg   = (tid & 3) * 8;
    const int b_k   = (tid & 15) * 2;
    const int b_px  = (tid >> 4) * 4;

    float acc[4][2][4] = {};
    const int KC = Kd >> 5;

    float4 ga[2][2], gb[2];
    {
        const float* g0 = A + (size_t)(m0 + a_row0) * Kd + a_kg;
        ga[0][0] = *(const float4*)g0;
        ga[0][1] = *(const float4*)(g0 + 4);
        const float* g1 = A + (size_t)(m0 + a_row0 + 64) * Kd + a_kg;
        ga[1][0] = *(const float4*)g1;
        ga[1][1] = *(const float4*)(g1 + 4);
        const float* gB = Bn + (size_t)b_k * HW + p0 + b_px;
        gb[0] = *(const float4*)gB;
        gb[1] = *(const float4*)(gB + HW);
    }

    for (int kc = 0; kc < KC; ++kc) {
        __syncthreads();
#pragma unroll
        for (int t = 0; t < 2; ++t) {
            int row = a_row0 + t * 64;
            uint4 hi, lo;
            split8(ga[t][0], ga[t][1], hi, lo);
            *(uint4*)&As_hi[row][a_kg] = hi;
            *(uint4*)&As_lo[row][a_kg] = lo;
        }
        {
            float vk[4]  = {gb[0].x, gb[0].y, gb[0].z, gb[0].w};
            float vk1[4] = {gb[1].x, gb[1].y, gb[1].z, gb[1].w};
#pragma unroll
            for (int j = 0; j < 4; ++j) {
                uint32_t hi, lo;
                split2(vk[j], vk1[j], hi, lo);
                *(uint32_t*)&Bs_hi[b_px + j][b_k] = hi;
                *(uint32_t*)&Bs_lo[b_px + j][b_k] = lo;
            }
        }
        __syncthreads();

        if (kc + 1 < KC) {
            const int k0 = (kc + 1) << 5;
            const float* g0 = A + (size_t)(m0 + a_row0) * Kd + k0 + a_kg;
            ga[0][0] = *(const float4*)g0;
            ga[0][1] = *(const float4*)(g0 + 4);
            const float* g1 = A + (size_t)(m0 + a_row0 + 64) * Kd + k0 + a_kg;
            ga[1][0] = *(const float4*)g1;
            ga[1][1] = *(const float4*)(g1 + 4);
            const float* gB = Bn + (size_t)(k0 + b_k) * HW + p0 + b_px;
            gb[0] = *(const float4*)gB;
            gb[1] = *(const float4*)(gB + HW);
        }

#pragma unroll
        for (int ks = 0; ks < 32; ks += 16) {
            uint32_t bf_hi[4], bf_lo[4];   // [nf0:{0,1}, nf1:{2,3}]
            {
                int nb = warp_n * 16;
                ldsm_x4(bf_hi, b_addr4(Bs_hi, nb, ks, lid));
                ldsm_x4(bf_lo, b_addr4(Bs_lo, nb, ks, lid));
            }
#pragma unroll
            for (int mf = 0; mf < 4; ++mf) {
                int mb = warp_m * 64 + mf * 16;
                uint32_t ah[4], al[4];
                ldsm_x4(ah, a_addr(As_hi, mb, ks, lid));
                ldsm_x4(al, a_addr(As_lo, mb, ks, lid));
#pragma unroll
                for (int nf = 0; nf < 2; ++nf) {
                    mma16816(acc[mf][nf], ah, bf_hi + nf * 2);
                    mma16816(acc[mf][nf], ah, bf_lo + nf * 2);
                    mma16816(acc[mf][nf], al, bf_hi + nf * 2);
                }
            }
        }
    }

#pragma unroll
    for (int mf = 0; mf < 4; ++mf) {
#pragma unroll
        for (int nf = 0; nf < 2; ++nf) {
            int m  = m0 + warp_m * 64 + mf * 16 + q;
            int px = p0 + warp_n * 16 + nf * 8 + 2 * r;
#pragma unroll
            for (int half = 0; half < 2; ++half) {
                int mm = m + half * 8;
                float c0 = acc[mf][nf][half * 2 + 0];
                float c1 = acc[mf][nf][half * 2 + 1];
                float bb = bias[mm];
                size_t base = ((size_t)n * M + mm) * HW + px;
                if (resid) {
                    float2 rv = *(const float2*)(resid + base);
                    c0 += rv.x;
                    c1 += rv.y;
                }
                float2 o;
                o.x = fmaxf(c0 + bb, 0.f);
                o.y = fmaxf(c1 + bb, 0.f);
                *(float2*)(C + base) = o;
            }
        }
    }
}

// ---------------------------------------------------------------------------
// Offset conv: 3x3 SAME, CB=256 -> 18 channels (unchanged)
// ---------------------------------------------------------------------------
__global__ void offset_conv_kernel(const float* __restrict__ w_off,
                                   const float* __restrict__ b_off) {
    __shared__ float red[8][64][18];
    const int n  = blockIdx.y;
    const int p0 = blockIdx.x * 64;
    const int tid = threadIdx.x;
    const int g  = tid >> 5;
    const int lx = tid & 31;

    float acc[2][18];
#pragma unroll
    for (int qq = 0; qq < 2; ++qq)
#pragma unroll
        for (int oc = 0; oc < 18; ++oc) acc[qq][oc] = 0.f;

    for (int ci = g; ci < CB; ci += 8) {
        const float* rb = g_r + ((size_t)n * CB + ci) * HW;
        float v[2][9];
#pragma unroll
        for (int qq = 0; qq < 2; ++qq) {
            int p = p0 + lx + qq * 32;
            int h = p / Ww, w = p % Ww;
#pragma unroll
            for (int t = 0; t < 9; ++t) {
                int y = h + t / 3 - 1;
                int x = w + t % 3 - 1;
                v[qq][t] = (y >= 0 && y < Hh && x >= 0 && x < Ww) ? rb[y * Ww + x] : 0.f;
            }
        }
        const float* wb = w_off + ci * 9;
#pragma unroll
        for (int oc = 0; oc < 18; ++oc) {
#pragma unroll
            for (int t = 0; t < 9; ++t) {
                float wv = wb[oc * (CB * 9) + t];
                acc[0][oc] += wv * v[0][t];
                acc[1][oc] += wv * v[1][t];
            }
        }
    }

#pragma unroll
    for (int qq = 0; qq < 2; ++qq)
#pragma unroll
        for (int oc = 0; oc < 18; ++oc)
            red[g][lx + qq * 32][oc] = acc[qq][oc];
    __syncthreads();

    for (int i = tid; i < 64 * 18; i += 256) {
        int ps = i / 18, oc = i % 18;
        float s = b_off[oc];
#pragma unroll
        for (int g2 = 0; g2 < 8; ++g2) s += red[g2][ps][oc];
        g_off[((size_t)n * 18 + oc) * HW + p0 + ps] = s;
    }
}

// ===========================================================================
// Deformable 3x3 conv on tensor cores (R6 pipeline + NHWC vectorized gather
// + B ldsm_x4). k = tap*256 + c; 36 chunks of 64 k.
// ===========================================================================
#define DPITCH 72
#define DSM_AS_H 0
#define DSM_AS_L 18432
#define DSM_BS_H 36864
#define DSM_BS_L 46080
#define DSM_BYTES 55296

__global__ __launch_bounds__(256, 2) void deform_mma_kernel(const float* __restrict__ b2) {
    extern __shared__ char dsm[];
    typedef __nv_bfloat16 (*tile_t)[DPITCH];
    tile_t As_h = (tile_t)(dsm + DSM_AS_H);
    tile_t As_l = (tile_t)(dsm + DSM_AS_L);
    tile_t Bs_h = (tile_t)(dsm + DSM_BS_H);
    tile_t Bs_l = (tile_t)(dsm + DSM_BS_L);

    const int pb = blockIdx.x * 64;
    const int m0 = blockIdx.y * 128;
    const int n  = blockIdx.z;
    const int tid = threadIdx.x;
    const int wid = tid >> 5;
    const int lid = tid & 31;
    const int q = lid >> 2;
    const int r = lid & 3;
    const int wm = wid & 3;
    const int wn = wid >> 2;

    const int gpx = tid & 63;
    const int gg  = tid >> 6;
    const int gcl = gg * 16;

    const float* rtbase = g_rt + (size_t)n * HW * CB;
    const float* offb   = g_off + (size_t)n * 18 * HW + pb + gpx;
    const int gh = (pb + gpx) / Ww;
    const int gw = (pb + gpx) % Ww;

    float acc[2][4][4] = {};

    int   idx0, idx1, idx2, idx3;
    float wt0, wt1, wt2, wt3;
#define BILIN(tap_) do {                                                       \
    float dy = offb[(size_t)((tap_) * 2 + 0) * HW];                            \
    float dx = offb[(size_t)((tap_) * 2 + 1) * HW];                            \
    float ys = (float)(gh + (tap_) / 3 - 1) + dy;                              \
    float xs = (float)(gw + (tap_) % 3 - 1) + dx;                              \
    float y0f = floorf(ys), x0f = floorf(xs);                                  \
    float wy1 = ys - y0f, wy0 = 1.f - wy1;                                     \
    float wx1 = xs - x0f, wx0 = 1.f - wx1;                                     \
    int y0 = (int)y0f, x0 = (int)x0f;                                          \
    int y1 = y0 + 1, x1 = x0 + 1;                                              \
    bool vy0 = (y0 >= 0) && (y0 < Hh);                                         \
    bool vy1 = (y1 >= 0) && (y1 < Hh);                                         \
    bool vx0 = (x0 >= 0) && (x0 < Ww);                                         \
    bool vx1 = (x1 >= 0) && (x1 < Ww);                                         \
    int yc0 = min(max(y0, 0), Hh - 1), yc1 = min(max(y1, 0), Hh - 1);          \
    int xc0 = min(max(x0, 0), Ww - 1), xc1 = min(max(x1, 0), Ww - 1);          \
    idx0 = yc0 * Ww + xc0;  wt0 = (vy0 && vx0) ? wy0 * wx0 : 0.f;              \
    idx1 = yc0 * Ww + xc1;  wt1 = (vy0 && vx1) ? wy0 * wx1 : 0.f;              \
    idx2 = yc1 * Ww + xc0;  wt2 = (vy1 && vx0) ? wy1 * wx0 : 0.f;              \
    idx3 = yc1 * Ww + xc1;  wt3 = (vy1 && vx1) ? wy1 * wx1 : 0.f;              \
} while (0)

    float v[16];
    // NHWC gather: 4 corners x 16 consecutive channels via float4 loads
#define GATHER(c0_) do {                                                       \
    const float4* rb0 = (const float4*)(rtbase + (size_t)idx0 * CB + (c0_) + gcl); \
    const float4* rb1 = (const float4*)(rtbase + (size_t)idx1 * CB + (c0_) + gcl); \
    const float4* rb2 = (const float4*)(rtbase + (size_t)idx2 * CB + (c0_) + gcl); \
    const float4* rb3 = (const float4*)(rtbase + (size_t)idx3 * CB + (c0_) + gcl); \
    _Pragma("unroll")                                                          \
    for (int j4 = 0; j4 < 4; ++j4) {                                           \
        float4 a0 = __ldg(rb0 + j4);                                           \
        float4 a1 = __ldg(rb1 + j4);                                           \
        float4 a2 = __ldg(rb2 + j4);                                           \
        float4 a3 = __ldg(rb3 + j4);                                           \
        v[4 * j4 + 0] = wt0 * a0.x + wt1 * a1.x + wt2 * a2.x + wt3 * a3.x;     \
        v[4 * j4 + 1] = wt0 * a0.y + wt1 * a1.y + wt2 * a2.y + wt3 * a3.y;     \
        v[4 * j4 + 2] = wt0 * a0.z + wt1 * a1.z + wt2 * a2.z + wt3 * a3.z;     \
        v[4 * j4 + 3] = wt0 * a0.w + wt1 * a1.w + wt2 * a2.w + wt3 * a3.w;     \
    }                                                                          \
} while (0)

    // prologue: chunk 0
    BILIN(0);
    GATHER(0);
    int tap_cur = 0;

    for (int ch = 0; ch < 36; ++ch) {
        const int tap = ch >> 2;
        const int k0  = tap * 256 + (ch & 3) * 64;
        __syncthreads();  // previous MMA done with smem

        // store gathered values -> Bs (split bf16 hi/lo)
        {
            uint4 h0, h1, l0, l1;
            split2(v[0],  v[1],  h0.x, l0.x);
            split2(v[2],  v[3],  h0.y, l0.y);
            split2(v[4],  v[5],  h0.z, l0.z);
            split2(v[6],  v[7],  h0.w, l0.w);
            split2(v[8],  v[9],  h1.x, l1.x);
            split2(v[10], v[11], h1.y, l1.y);
            split2(v[12], v[13], h1.z, l1.z);
            split2(v[14], v[15], h1.w, l1.w);
            *(uint4*)&Bs_h[gpx][gcl]     = h0;
            *(uint4*)&Bs_h[gpx][gcl + 8] = h1;
            *(uint4*)&Bs_l[gpx][gcl]     = l0;
            *(uint4*)&Bs_l[gpx][gcl + 8] = l1;
        }
        // stage weights via cp.async
#pragma unroll
        for (int pass = 0; pass < 4; ++pass) {
            int id   = tid + pass * 256;
            int row  = id >> 3;
            int col  = (id & 7) * 8;
            size_t goff = (size_t)(m0 + row) * KD + k0 + col;
            cp16((uint32_t)__cvta_generic_to_shared(&As_h[row][col]), g_w2h + goff);
            cp16((uint32_t)__cvta_generic_to_shared(&As_l[row][col]), g_w2l + goff);
        }
        CP_COMMIT();

        // prefetch next chunk's gather while cp.async proceeds
        if (ch + 1 < 36) {
            int ntap = (ch + 1) >> 2;
            if (ntap != tap_cur) {
                BILIN(ntap);
                tap_cur = ntap;
            }
            GATHER(((ch + 1) & 3) * 64);
        }

        CP_WAIT0();
        __syncthreads();

        // MMA: 4 k16 steps (B via ldsm_x4: 2 nf per ldsm)
#pragma unroll
        for (int ks = 0; ks < 64; ks += 16) {
            uint32_t bh[8], bl[8];   // nf = [0..3], pairs at 2*nf
            ldsm_x4(bh,     b_addr4(Bs_h, wn * 32,      ks, lid));
            ldsm_x4(bh + 4, b_addr4(Bs_h, wn * 32 + 16, ks, lid));
            ldsm_x4(bl,     b_addr4(Bs_l, wn * 32,      ks, lid));
            ldsm_x4(bl + 4, b_addr4(Bs_l, wn * 32 + 16, ks, lid));
#pragma unroll
            for (int mf = 0; mf < 2; ++mf) {
                int mb = wm * 32 + mf * 16;
                uint32_t ah[4], al[4];
                ldsm_x4(ah, a_addr(As_h, mb, ks, lid));
                ldsm_x4(al, a_addr(As_l, mb, ks, lid));
#pragma unroll
                for (int nf = 0; nf < 4; ++nf) {
                    mma16816(acc[mf][nf], ah, bh + nf * 2);
                    mma16816(acc[mf][nf], ah, bl + nf * 2);
                    mma16816(acc[mf][nf], al, bh + nf * 2);
                }
            }
        }
    }

    // epilogue: bias + relu -> g_r2
#pragma unroll
    for (int mf = 0; mf < 2; ++mf) {
#pragma unroll
        for (int half = 0; half < 2; ++half) {
            int o = m0 + wm * 32 + mf * 16 + q + half * 8;
            float bb = b2[o];
            float* orow = g_r2 + ((size_t)n * CB + o) * HW + pb;
#pragma unroll
            for (int nf = 0; nf < 4; ++nf) {
                int px = wn * 32 + nf * 8 + 2 * r;
                float2 ov;
                ov.x = fmaxf(acc[mf][nf][half * 2 + 0] + bb, 0.f);
                ov.y = fmaxf(acc[mf][nf][half * 2 + 1] + bb, 0.f);
                *(float2*)(orow + px) = ov;
            }
        }
    }
}

// ---------------------------------------------------------------------------
extern "C" void kernel_launch(void* const* d_in, const int* in_sizes, int n_in,
                              void* d_out, int out_size) {
    const float* x     = (const float*)d_in[0];
    const float* w1    = (const float*)d_in[1];
    const float* b1    = (const float*)d_in[2];
    const float* w_off = (const float*)d_in[3];
    const float* b_off = (const float*)d_in[4];
    const float* w2    = (const float*)d_in[5];
    const float* b2    = (const float*)d_in[6];
    const float* w3    = (const float*)d_in[7];
    const float* b3    = (const float*)d_in[8];
    float* out = (float*)d_out;

    float *r_ptr, *r2_ptr;
    cudaGetSymbolAddress((void**)&r_ptr, g_r);
    cudaGetSymbolAddress((void**)&r2_ptr, g_r2);

    cudaFuncSetAttribute(deform_mma_kernel,
                         cudaFuncAttributeMaxDynamicSharedMemorySize, DSM_BYTES);

    // w2 -> bf16 hi/lo, k = tap*256+c
    prep_w2_kernel<<<(CB * KD + 255) / 256, 256>>>(w2);

    // conv1: 1024 -> 256, relu (HMMA split-bf16)
    gemm_tc_kernel<<<dim3(HW / 64, CB / 128, Nn), 256>>>(
        w1, x, b1, nullptr, r_ptr, CB, CIN);

    // NCHW -> NHWC copy of conv1 output (for vectorized deform gather)
    nchw2nhwc_kernel<<<dim3(HW / 32, CB / 32, Nn), dim3(32, 8)>>>();

    // offset conv 3x3: 256 -> 18
    offset_conv_kernel<<<dim3(HW / 64, Nn), 256>>>(w_off, b_off);

    // deformable conv 3x3: 256 -> 256, relu (HMMA, NHWC gather)
    deform_mma_kernel<<<dim3(HW / 64, 2, Nn), 256, DSM_BYTES>>>(b2);

    // conv3: 256 -> 1024 + x residual, relu (HMMA split-bf16)
    gemm_tc_kernel<<<dim3(HW / 64, CIN / 128, Nn), 256>>>(
        w3, r2_ptr, b3, x, out, CIN, CB);
}

// round 9
// speedup vs baseline: 1.2622x; 1.2622x over previous
#include <cuda_runtime.h>
#include <cuda_bf16.h>
#include <math.h>
#include <stdint.h>

#define Nn   4
#define CIN  1024
#define CB   256
#define Hh   56
#define Ww   56
#define HW   3136
#define KT   9
#define KD   (CB * KT)   // 2304

// Scratch (device globals: allocation-free rule)
__device__ float g_r  [Nn * CB * HW];     // conv1 output (relu)
__device__ float g_off[Nn * 2 * KT * HW]; // offset conv output
__device__ float g_r2 [Nn * CB * HW];     // deform conv output (relu)
__device__ __nv_bfloat16 g_w2h[CB * KD];  // w2 split hi, [o][tap*256+c]
__device__ __nv_bfloat16 g_w2l[CB * KD];  // w2 split lo

// ---------------------------------------------------------------------------
// helpers
// ---------------------------------------------------------------------------
__device__ __forceinline__ void split2(float x, float y, uint32_t& hi, uint32_t& lo) {
    __nv_bfloat16 xh = __float2bfloat16(x);
    __nv_bfloat16 yh = __float2bfloat16(y);
    __nv_bfloat16 xl = __float2bfloat16(x - __bfloat162float(xh));
    __nv_bfloat16 yl = __float2bfloat16(y - __bfloat162float(yh));
    hi = ((uint32_t)__bfloat16_as_ushort(yh) << 16) | __bfloat16_as_ushort(xh);
    lo = ((uint32_t)__bfloat16_as_ushort(yl) << 16) | __bfloat16_as_ushort(xl);
}
__device__ __forceinline__ void split8(const float4& a, const float4& b,
                                       uint4& hi, uint4& lo) {
    split2(a.x, a.y, hi.x, lo.x);
    split2(a.z, a.w, hi.y, lo.y);
    split2(b.x, b.y, hi.z, lo.z);
    split2(b.z, b.w, hi.w, lo.w);
}

__device__ __forceinline__ void mma16816(float* c, const uint32_t* a, const uint32_t* b) {
    asm volatile(
        "mma.sync.aligned.m16n8k16.row.col.f32.bf16.bf16.f32 "
        "{%0,%1,%2,%3}, {%4,%5,%6,%7}, {%8,%9}, {%0,%1,%2,%3};"
        : "+f"(c[0]), "+f"(c[1]), "+f"(c[2]), "+f"(c[3])
        : "r"(a[0]), "r"(a[1]), "r"(a[2]), "r"(a[3]), "r"(b[0]), "r"(b[1]));
}

__device__ __forceinline__ void ldsm_x4(uint32_t* r, uint32_t addr) {
    asm volatile("ldmatrix.sync.aligned.m8n8.x4.shared.b16 {%0,%1,%2,%3}, [%4];"
                 : "=r"(r[0]), "=r"(r[1]), "=r"(r[2]), "=r"(r[3]) : "r"(addr));
}
__device__ __forceinline__ void ldsm_x2(uint32_t* r, uint32_t addr) {
    asm volatile("ldmatrix.sync.aligned.m8n8.x2.shared.b16 {%0,%1}, [%2];"
                 : "=r"(r[0]), "=r"(r[1]) : "r"(addr));
}
template <int P>
__device__ __forceinline__ uint32_t a_addr(const __nv_bfloat16 (*S)[P], int mb, int ks, int ln) {
    int row = mb + (ln & 7) + ((ln >> 3) & 1) * 8;
    int col = ks + (ln >> 4) * 8;
    return (uint32_t)__cvta_generic_to_shared(&S[row][col]);
}
template <int P>
__device__ __forceinline__ uint32_t b_addr(const __nv_bfloat16 (*S)[P], int nb, int ks, int ln) {
    int l = ln & 15;
    int row = nb + (l & 7);
    int col = ks + ((l >> 3) & 1) * 8;
    return (uint32_t)__cvta_generic_to_shared(&S[row][col]);
}
__device__ __forceinline__ void cp16(uint32_t saddr, const void* g) {
    asm volatile("cp.async.ca.shared.global [%0], [%1], 16;"
                 :: "r"(saddr), "l"(g) : "memory");
}
#define CP_COMMIT() asm volatile("cp.async.commit_group;" ::: "memory")
#define CP_WAIT0()  asm volatile("cp.async.wait_group 0;" ::: "memory")

// ---------------------------------------------------------------------------
// w2 (o,c,kh,kw) fp32 -> bf16 hi/lo at [o][tap*256+c]
// ---------------------------------------------------------------------------
__global__ void prep_w2_kernel(const float* __restrict__ w2) {
    int i = blockIdx.x * 256 + threadIdx.x;
    if (i < CB * KD) {
        int o = i / KD;
        int k = i % KD;
        int tap = k >> 8;
        int c   = k & 255;
        float v = w2[(o * CB + c) * KT + tap];
        __nv_bfloat16 h = __float2bfloat16(v);
        g_w2h[i] = h;
        g_w2l[i] = __float2bfloat16(v - __bfloat162float(h));
    }
}

// ===========================================================================
// Tensor-core (HMMA) GEMM for the 1x1 convs (R6-proven version).
// ===========================================================================
#define BKP 40

__global__ __launch_bounds__(256) void gemm_tc_kernel(
        const float* __restrict__ A, const float* __restrict__ Bx,
        const float* __restrict__ bias, const float* __restrict__ resid,
        float* __restrict__ C, int M, int Kd) {
    __shared__ __nv_bfloat16 As_hi[128][BKP];
    __shared__ __nv_bfloat16 As_lo[128][BKP];
    __shared__ __nv_bfloat16 Bs_hi[64][BKP];
    __shared__ __nv_bfloat16 Bs_lo[64][BKP];

    const int n  = blockIdx.z;
    const int m0 = blockIdx.y * 128;
    const int p0 = blockIdx.x * 64;
    const int tid = threadIdx.x;
    const int wid = tid >> 5;
    const int lid = tid & 31;
    const int q = lid >> 2;
    const int r = lid & 3;
    const int warp_m = wid >> 2;
    const int warp_n = wid & 3;
    const float* Bn = Bx + (size_t)n * Kd * HW;

    const int a_row0 = tid >> 2;
    const int a_kg   = (tid & 3) * 8;
    const int b_k   = (tid & 15) * 2;
    const int b_px  = (tid >> 4) * 4;

    float acc[4][2][4] = {};
    const int KC = Kd >> 5;

    float4 ga[2][2], gb[2];
    {
        const float* g0 = A + (size_t)(m0 + a_row0) * Kd + a_kg;
        ga[0][0] = *(const float4*)g0;
        ga[0][1] = *(const float4*)(g0 + 4);
        const float* g1 = A + (size_t)(m0 + a_row0 + 64) * Kd + a_kg;
        ga[1][0] = *(const float4*)g1;
        ga[1][1] = *(const float4*)(g1 + 4);
        const float* gB = Bn + (size_t)b_k * HW + p0 + b_px;
        gb[0] = *(const float4*)gB;
        gb[1] = *(const float4*)(gB + HW);
    }

    for (int kc = 0; kc < KC; ++kc) {
        __syncthreads();
#pragma unroll
        for (int t = 0; t < 2; ++t) {
            int row = a_row0 + t * 64;
            uint4 hi, lo;
            split8(ga[t][0], ga[t][1], hi, lo);
            *(uint4*)&As_hi[row][a_kg] = hi;
            *(uint4*)&As_lo[row][a_kg] = lo;
        }
        {
            float vk[4]  = {gb[0].x, gb[0].y, gb[0].z, gb[0].w};
            float vk1[4] = {gb[1].x, gb[1].y, gb[1].z, gb[1].w};
#pragma unroll
            for (int j = 0; j < 4; ++j) {
                uint32_t hi, lo;
                split2(vk[j], vk1[j], hi, lo);
                *(uint32_t*)&Bs_hi[b_px + j][b_k] = hi;
                *(uint32_t*)&Bs_lo[b_px + j][b_k] = lo;
            }
        }
        __syncthreads();

        if (kc + 1 < KC) {
            const int k0 = (kc + 1) << 5;
            const float* g0 = A + (size_t)(m0 + a_row0) * Kd + k0 + a_kg;
            ga[0][0] = *(const float4*)g0;
            ga[0][1] = *(const float4*)(g0 + 4);
            const float* g1 = A + (size_t)(m0 + a_row0 + 64) * Kd + k0 + a_kg;
            ga[1][0] = *(const float4*)g1;
            ga[1][1] = *(const float4*)(g1 + 4);
            const float* gB = Bn + (size_t)(k0 + b_k) * HW + p0 + b_px;
            gb[0] = *(const float4*)gB;
            gb[1] = *(const float4*)(gB + HW);
        }

#pragma unroll
        for (int ks = 0; ks < 32; ks += 16) {
            uint32_t bf_hi[2][2], bf_lo[2][2];
#pragma unroll
            for (int nf = 0; nf < 2; ++nf) {
                int nb = warp_n * 16 + nf * 8;
                ldsm_x2(bf_hi[nf], b_addr(Bs_hi, nb, ks, lid));
                ldsm_x2(bf_lo[nf], b_addr(Bs_lo, nb, ks, lid));
            }
#pragma unroll
            for (int mf = 0; mf < 4; ++mf) {
                int mb = warp_m * 64 + mf * 16;
                uint32_t ah[4], al[4];
                ldsm_x4(ah, a_addr(As_hi, mb, ks, lid));
                ldsm_x4(al, a_addr(As_lo, mb, ks, lid));
#pragma unroll
                for (int nf = 0; nf < 2; ++nf) {
                    mma16816(acc[mf][nf], ah, bf_hi[nf]);
                    mma16816(acc[mf][nf], ah, bf_lo[nf]);
                    mma16816(acc[mf][nf], al, bf_hi[nf]);
                }
            }
        }
    }

#pragma unroll
    for (int mf = 0; mf < 4; ++mf) {
#pragma unroll
        for (int nf = 0; nf < 2; ++nf) {
            int m  = m0 + warp_m * 64 + mf * 16 + q;
            int px = p0 + warp_n * 16 + nf * 8 + 2 * r;
#pragma unroll
            for (int half = 0; half < 2; ++half) {
                int mm = m + half * 8;
                float c0 = acc[mf][nf][half * 2 + 0];
                float c1 = acc[mf][nf][half * 2 + 1];
                float bb = bias[mm];
                size_t base = ((size_t)n * M + mm) * HW + px;
                if (resid) {
                    float2 rv = *(const float2*)(resid + base);
                    c0 += rv.x;
                    c1 += rv.y;
                }
                float2 o;
                o.x = fmaxf(c0 + bb, 0.f);
                o.y = fmaxf(c1 + bb, 0.f);
                *(float2*)(C + base) = o;
            }
        }
    }
}

// ---------------------------------------------------------------------------
// Offset conv: 3x3 SAME, CB=256 -> 18 ch. 32 px/block (2x parallelism, half
// the smem of the old version): 8 ci-groups x 32 lanes, 1 px x 32 ch each.
// ---------------------------------------------------------------------------
__global__ __launch_bounds__(256) void offset_conv_kernel(
        const float* __restrict__ w_off, const float* __restrict__ b_off) {
    __shared__ float red[8][32][18];
    const int n  = blockIdx.y;
    const int p0 = blockIdx.x * 32;
    const int tid = threadIdx.x;
    const int g  = tid >> 5;   // ci group 0..7
    const int lx = tid & 31;   // pixel lane

    float acc[18];
#pragma unroll
    for (int oc = 0; oc < 18; ++oc) acc[oc] = 0.f;

    const int p = p0 + lx;
    const int h = p / Ww, w = p % Ww;

    for (int ci = g; ci < CB; ci += 8) {
        const float* rb = g_r + ((size_t)n * CB + ci) * HW;
        float v[9];
#pragma unroll
        for (int t = 0; t < 9; ++t) {
            int y = h + t / 3 - 1;
            int x = w + t % 3 - 1;
            v[t] = (y >= 0 && y < Hh && x >= 0 && x < Ww) ? __ldg(rb + y * Ww + x) : 0.f;
        }
        const float* wb = w_off + ci * 9;
#pragma unroll
        for (int oc = 0; oc < 18; ++oc) {
#pragma unroll
            for (int t = 0; t < 9; ++t)
                acc[oc] += __ldg(wb + oc * (CB * 9) + t) * v[t];
        }
    }

#pragma unroll
    for (int oc = 0; oc < 18; ++oc)
        red[g][lx][oc] = acc[oc];
    __syncthreads();

    for (int i = tid; i < 32 * 18; i += 256) {
        int ps = i / 18, oc = i % 18;
        float s = b_off[oc];
#pragma unroll
        for (int g2 = 0; g2 < 8; ++g2) s += red[g2][ps][oc];
        g_off[((size_t)n * 18 + oc) * HW + p0 + ps] = s;
    }
}

// ===========================================================================
// Deformable 3x3 conv on tensor cores (R6-proven version):
//  - gather for chunk i+1 prefetched into regs during MMA of chunk i
//  - weights staged via cp.async; ldmatrix fragment loads
// k = tap*256 + c; chunks of 64 k; 36 chunks.
// ===========================================================================
#define DPITCH 72
#define DSM_AS_H 0
#define DSM_AS_L 18432
#define DSM_BS_H 36864
#define DSM_BS_L 46080
#define DSM_BYTES 55296

__global__ __launch_bounds__(256, 2) void deform_mma_kernel(const float* __restrict__ b2) {
    extern __shared__ char dsm[];
    typedef __nv_bfloat16 (*tile_t)[DPITCH];
    tile_t As_h = (tile_t)(dsm + DSM_AS_H);
    tile_t As_l = (tile_t)(dsm + DSM_AS_L);
    tile_t Bs_h = (tile_t)(dsm + DSM_BS_H);
    tile_t Bs_l = (tile_t)(dsm + DSM_BS_L);

    const int pb = blockIdx.x * 64;
    const int m0 = blockIdx.y * 128;
    const int n  = blockIdx.z;
    const int tid = threadIdx.x;
    const int wid = tid >> 5;
    const int lid = tid & 31;
    const int q = lid >> 2;
    const int r = lid & 3;
    const int wm = wid & 3;
    const int wn = wid >> 2;

    const int gpx = tid & 63;
    const int gg  = tid >> 6;
    const int gcl = gg * 16;

    const float* fbase = g_r + (size_t)n * CB * HW;
    const float* offb  = g_off + (size_t)n * 18 * HW + pb + gpx;
    const int gh = (pb + gpx) / Ww;
    const int gw = (pb + gpx) % Ww;

    float acc[2][4][4] = {};

    int   idx0, idx1, idx2, idx3;
    float wt0, wt1, wt2, wt3;
#define BILIN(tap_) do {                                                       \
    float dy = offb[(size_t)((tap_) * 2 + 0) * HW];                            \
    float dx = offb[(size_t)((tap_) * 2 + 1) * HW];                            \
    float ys = (float)(gh + (tap_) / 3 - 1) + dy;                              \
    float xs = (float)(gw + (tap_) % 3 - 1) + dx;                              \
    float y0f = floorf(ys), x0f = floorf(xs);                                  \
    float wy1 = ys - y0f, wy0 = 1.f - wy1;                                     \
    float wx1 = xs - x0f, wx0 = 1.f - wx1;                                     \
    int y0 = (int)y0f, x0 = (int)x0f;                                          \
    int y1 = y0 + 1, x1 = x0 + 1;                                              \
    bool vy0 = (y0 >= 0) && (y0 < Hh);                                         \
    bool vy1 = (y1 >= 0) && (y1 < Hh);                                         \
    bool vx0 = (x0 >= 0) && (x0 < Ww);                                         \
    bool vx1 = (x1 >= 0) && (x1 < Ww);                                         \
    int yc0 = min(max(y0, 0), Hh - 1), yc1 = min(max(y1, 0), Hh - 1);          \
    int xc0 = min(max(x0, 0), Ww - 1), xc1 = min(max(x1, 0), Ww - 1);          \
    idx0 = yc0 * Ww + xc0;  wt0 = (vy0 && vx0) ? wy0 * wx0 : 0.f;              \
    idx1 = yc0 * Ww + xc1;  wt1 = (vy0 && vx1) ? wy0 * wx1 : 0.f;              \
    idx2 = yc1 * Ww + xc0;  wt2 = (vy1 && vx0) ? wy1 * wx0 : 0.f;              \
    idx3 = yc1 * Ww + xc1;  wt3 = (vy1 && vx1) ? wy1 * wx1 : 0.f;              \
} while (0)

    float v[16];
#define GATHER(c0_) do {                                                       \
    _Pragma("unroll")                                                          \
    for (int j = 0; j < 16; ++j) {                                             \
        const float* f = fbase + (size_t)((c0_) + gcl + j) * HW;               \
        v[j] = wt0 * __ldg(f + idx0) + wt1 * __ldg(f + idx1)                   \
             + wt2 * __ldg(f + idx2) + wt3 * __ldg(f + idx3);                  \
    }                                                                          \
} while (0)

    // prologue: chunk 0
    BILIN(0);
    GATHER(0);
    int tap_cur = 0;

    for (int ch = 0; ch < 36; ++ch) {
        const int tap = ch >> 2;
        const int k0  = tap * 256 + (ch & 3) * 64;
        __syncthreads();  // previous MMA done with smem

        // store gathered values -> Bs (split bf16 hi/lo)
        {
            uint4 h0, h1, l0, l1;
            split2(v[0],  v[1],  h0.x, l0.x);
            split2(v[2],  v[3],  h0.y, l0.y);
            split2(v[4],  v[5],  h0.z, l0.z);
            split2(v[6],  v[7],  h0.w, l0.w);
            split2(v[8],  v[9],  h1.x, l1.x);
            split2(v[10], v[11], h1.y, l1.y);
            split2(v[12], v[13], h1.z, l1.z);
            split2(v[14], v[15], h1.w, l1.w);
            *(uint4*)&Bs_h[gpx][gcl]     = h0;
            *(uint4*)&Bs_h[gpx][gcl + 8] = h1;
            *(uint4*)&Bs_l[gpx][gcl]     = l0;
            *(uint4*)&Bs_l[gpx][gcl + 8] = l1;
        }
        // stage weights via cp.async
#pragma unroll
        for (int pass = 0; pass < 4; ++pass) {
            int id   = tid + pass * 256;
            int row  = id >> 3;
            int col  = (id & 7) * 8;
            size_t goff = (size_t)(m0 + row) * KD + k0 + col;
            cp16((uint32_t)__cvta_generic_to_shared(&As_h[row][col]), g_w2h + goff);
            cp16((uint32_t)__cvta_generic_to_shared(&As_l[row][col]), g_w2l + goff);
        }
        CP_COMMIT();

        // prefetch next chunk's gather while cp.async proceeds
        if (ch + 1 < 36) {
            int ntap = (ch + 1) >> 2;
            if (ntap != tap_cur) {
                BILIN(ntap);
                tap_cur = ntap;
            }
            GATHER(((ch + 1) & 3) * 64);
        }

        CP_WAIT0();
        __syncthreads();

        // MMA: 4 k16 steps over the 64-k chunk (ldmatrix fragments)
#pragma unroll
        for (int ks = 0; ks < 64; ks += 16) {
            uint32_t bh[4][2], bl[4][2];
#pragma unroll
            for (int nf = 0; nf < 4; ++nf) {
                int nb = wn * 32 + nf * 8;
                ldsm_x2(bh[nf], b_addr(Bs_h, nb, ks, lid));
                ldsm_x2(bl[nf], b_addr(Bs_l, nb, ks, lid));
            }
#pragma unroll
            for (int mf = 0; mf < 2; ++mf) {
                int mb = wm * 32 + mf * 16;
                uint32_t ah[4], al[4];
                ldsm_x4(ah, a_addr(As_h, mb, ks, lid));
                ldsm_x4(al, a_addr(As_l, mb, ks, lid));
#pragma unroll
                for (int nf = 0; nf < 4; ++nf) {
                    mma16816(acc[mf][nf], ah, bh[nf]);
                    mma16816(acc[mf][nf], ah, bl[nf]);
                    mma16816(acc[mf][nf], al, bh[nf]);
                }
            }
        }
    }

    // epilogue: bias + relu -> g_r2
#pragma unroll
    for (int mf = 0; mf < 2; ++mf) {
#pragma unroll
        for (int half = 0; half < 2; ++half) {
            int o = m0 + wm * 32 + mf * 16 + q + half * 8;
            float bb = b2[o];
            float* orow = g_r2 + ((size_t)n * CB + o) * HW + pb;
#pragma unroll
            for (int nf = 0; nf < 4; ++nf) {
                int px = wn * 32 + nf * 8 + 2 * r;
                float2 ov;
                ov.x = fmaxf(acc[mf][nf][half * 2 + 0] + bb, 0.f);
                ov.y = fmaxf(acc[mf][nf][half * 2 + 1] + bb, 0.f);
                *(float2*)(orow + px) = ov;
            }
        }
    }
}

// ---------------------------------------------------------------------------
extern "C" void kernel_launch(void* const* d_in, const int* in_sizes, int n_in,
                              void* d_out, int out_size) {
    const float* x     = (const float*)d_in[0];
    const float* w1    = (const float*)d_in[1];
    const float* b1    = (const float*)d_in[2];
    const float* w_off = (const float*)d_in[3];
    const float* b_off = (const float*)d_in[4];
    const float* w2    = (const float*)d_in[5];
    const float* b2    = (const float*)d_in[6];
    const float* w3    = (const float*)d_in[7];
    const float* b3    = (const float*)d_in[8];
    float* out = (float*)d_out;

    float *r_ptr, *r2_ptr;
    cudaGetSymbolAddress((void**)&r_ptr, g_r);
    cudaGetSymbolAddress((void**)&r2_ptr, g_r2);

    cudaFuncSetAttribute(deform_mma_kernel,
                         cudaFuncAttributeMaxDynamicSharedMemorySize, DSM_BYTES);

    // w2 -> bf16 hi/lo, k = tap*256+c
    prep_w2_kernel<<<(CB * KD + 255) / 256, 256>>>(w2);

    // conv1: 1024 -> 256, relu (HMMA split-bf16)
    gemm_tc_kernel<<<dim3(HW / 64, CB / 128, Nn), 256>>>(
        w1, x, b1, nullptr, r_ptr, CB, CIN);

    // offset conv 3x3: 256 -> 18 (higher-occupancy version)
    offset_conv_kernel<<<dim3(HW / 32, Nn), 256>>>(w_off, b_off);

    // deformable conv 3x3: 256 -> 256, relu (HMMA, R6 pipeline)
    deform_mma_kernel<<<dim3(HW / 64, 2, Nn), 256, DSM_BYTES>>>(b2);

    // conv3: 256 -> 1024 + x residual, relu (HMMA split-bf16)
    gemm_tc_kernel<<<dim3(HW / 64, CIN / 128, Nn), 256>>>(
        w3, r2_ptr, b3, x, out, CIN, CB);
}

// round 10
// speedup vs baseline: 1.3389x; 1.0608x over previous
#include <cuda_runtime.h>
#include <cuda_bf16.h>
#include <math.h>
#include <stdint.h>

#define Nn   4
#define CIN  1024
#define CB   256
#define Hh   56
#define Ww   56
#define HW   3136
#define KT   9
#define KD   (CB * KT)   // 2304

// Scratch (device globals: allocation-free rule)
__device__ float g_r  [Nn * CB * HW];     // conv1 output (relu)
__device__ float g_off[Nn * 2 * KT * HW]; // offset conv output
__device__ float g_r2 [Nn * CB * HW];     // deform conv output (relu)
__device__ __nv_bfloat16 g_w2h[CB * KD];  // w2 split hi, [o][tap*256+c]
__device__ __nv_bfloat16 g_w2l[CB * KD];  // w2 split lo
__device__ __nv_bfloat16 g_w1h[CB * CIN]; // w1 split hi [256][1024]
__device__ __nv_bfloat16 g_w1l[CB * CIN];
__device__ __nv_bfloat16 g_w3h[CIN * CB]; // w3 split hi [1024][256]
__device__ __nv_bfloat16 g_w3l[CIN * CB];

// ---------------------------------------------------------------------------
// helpers
// ---------------------------------------------------------------------------
__device__ __forceinline__ void split2(float x, float y, uint32_t& hi, uint32_t& lo) {
    __nv_bfloat16 xh = __float2bfloat16(x);
    __nv_bfloat16 yh = __float2bfloat16(y);
    __nv_bfloat16 xl = __float2bfloat16(x - __bfloat162float(xh));
    __nv_bfloat16 yl = __float2bfloat16(y - __bfloat162float(yh));
    hi = ((uint32_t)__bfloat16_as_ushort(yh) << 16) | __bfloat16_as_ushort(xh);
    lo = ((uint32_t)__bfloat16_as_ushort(yl) << 16) | __bfloat16_as_ushort(xl);
}

__device__ __forceinline__ void mma16816(float* c, const uint32_t* a, const uint32_t* b) {
    asm volatile(
        "mma.sync.aligned.m16n8k16.row.col.f32.bf16.bf16.f32 "
        "{%0,%1,%2,%3}, {%4,%5,%6,%7}, {%8,%9}, {%0,%1,%2,%3};"
        : "+f"(c[0]), "+f"(c[1]), "+f"(c[2]), "+f"(c[3])
        : "r"(a[0]), "r"(a[1]), "r"(a[2]), "r"(a[3]), "r"(b[0]), "r"(b[1]));
}

__device__ __forceinline__ void ldsm_x4(uint32_t* r, uint32_t addr) {
    asm volatile("ldmatrix.sync.aligned.m8n8.x4.shared.b16 {%0,%1,%2,%3}, [%4];"
                 : "=r"(r[0]), "=r"(r[1]), "=r"(r[2]), "=r"(r[3]) : "r"(addr));
}
__device__ __forceinline__ void ldsm_x2(uint32_t* r, uint32_t addr) {
    asm volatile("ldmatrix.sync.aligned.m8n8.x2.shared.b16 {%0,%1}, [%2];"
                 : "=r"(r[0]), "=r"(r[1]) : "r"(addr));
}
template <int P>
__device__ __forceinline__ uint32_t a_addr(const __nv_bfloat16 (*S)[P], int mb, int ks, int ln) {
    int row = mb + (ln & 7) + ((ln >> 3) & 1) * 8;
    int col = ks + (ln >> 4) * 8;
    return (uint32_t)__cvta_generic_to_shared(&S[row][col]);
}
template <int P>
__device__ __forceinline__ uint32_t b_addr(const __nv_bfloat16 (*S)[P], int nb, int ks, int ln) {
    int l = ln & 15;
    int row = nb + (l & 7);
    int col = ks + ((l >> 3) & 1) * 8;
    return (uint32_t)__cvta_generic_to_shared(&S[row][col]);
}
__device__ __forceinline__ void cp16(uint32_t saddr, const void* g) {
    asm volatile("cp.async.ca.shared.global [%0], [%1], 16;"
                 :: "r"(saddr), "l"(g) : "memory");
}
#define CP_COMMIT() asm volatile("cp.async.commit_group;" ::: "memory")
#define CP_WAIT0()  asm volatile("cp.async.wait_group 0;" ::: "memory")
#define CP_WAIT1()  asm volatile("cp.async.wait_group 1;" ::: "memory")

// ---------------------------------------------------------------------------
// weight prep: fp32 -> bf16 hi/lo
// ---------------------------------------------------------------------------
__global__ void prep_w2_kernel(const float* __restrict__ w2) {
    int i = blockIdx.x * 256 + threadIdx.x;
    if (i < CB * KD) {
        int o = i / KD;
        int k = i % KD;
        int tap = k >> 8;
        int c   = k & 255;
        float v = w2[(o * CB + c) * KT + tap];
        __nv_bfloat16 h = __float2bfloat16(v);
        g_w2h[i] = h;
        g_w2l[i] = __float2bfloat16(v - __bfloat162float(h));
    }
}
__global__ void prep_w_kernel(const float* __restrict__ w,
                              __nv_bfloat16* __restrict__ oh,
                              __nv_bfloat16* __restrict__ ol, int total) {
    int i = blockIdx.x * 256 + threadIdx.x;
    if (i < total) {
        float v = w[i];
        __nv_bfloat16 h = __float2bfloat16(v);
        oh[i] = h;
        ol[i] = __float2bfloat16(v - __bfloat162float(h));
    }
}

// ===========================================================================
// Tensor-core GEMM for 1x1 convs. BK=64, A pre-split bf16 staged via cp.async
// (2-stage A double buffer, committed one chunk ahead). B fp32 loaded
// px-major coalesced, split on the fly.
// ===========================================================================
#define GKP 72
#define G_AS_BYTES (128 * GKP * 2)          // 18432 per h/l tile
#define G_STAGE    (2 * G_AS_BYTES)         // 36864 per stage (h+l)
#define G_B_OFF    (2 * G_STAGE)            // 73728
#define G_BS_BYTES (64 * GKP * 2)           // 9216
#define GSM_BYTES  (G_B_OFF + 2 * G_BS_BYTES)  // 92160

__global__ __launch_bounds__(256) void gemm_tc_kernel(
        const __nv_bfloat16* __restrict__ Ah,
        const __nv_bfloat16* __restrict__ Al,
        const float* __restrict__ Bx,
        const float* __restrict__ bias, const float* __restrict__ resid,
        float* __restrict__ C, int M, int Kd) {
    extern __shared__ char gsm[];
    typedef __nv_bfloat16 (*tile_t)[GKP];
    tile_t Bs_h = (tile_t)(gsm + G_B_OFF);
    tile_t Bs_l = (tile_t)(gsm + G_B_OFF + G_BS_BYTES);

    const int n  = blockIdx.z;
    const int m0 = blockIdx.y * 128;
    const int p0 = blockIdx.x * 64;
    const int tid = threadIdx.x;
    const int wid = tid >> 5;
    const int lid = tid & 31;
    const int q = lid >> 2;
    const int r = lid & 3;
    const int warp_m = wid >> 2;
    const int warp_n = wid & 3;
    const float* Bn = Bx + (size_t)n * Kd * HW;

    // B-load role: px-major coalesced
    const int b_px = (tid & 15) * 4;     // 0..60
    const int b_kp = (tid >> 4) * 2;     // k-pair base 0..30 (+32 for second)

    float acc[4][2][4] = {};
    const int KC = Kd >> 6;

#define STAGE_A(s_, k0_) do {                                                  \
    tile_t _ah = (tile_t)(gsm + (s_) * G_STAGE);                               \
    tile_t _al = (tile_t)(gsm + (s_) * G_STAGE + G_AS_BYTES);                  \
    _Pragma("unroll")                                                          \
    for (int pass = 0; pass < 4; ++pass) {                                     \
        int id  = tid + pass * 256;                                            \
        int row = id >> 3;                                                     \
        int col = (id & 7) * 8;                                                \
        size_t goff = (size_t)(m0 + row) * Kd + (k0_) + col;                   \
        cp16((uint32_t)__cvta_generic_to_shared(&_ah[row][col]), Ah + goff);   \
        cp16((uint32_t)__cvta_generic_to_shared(&_al[row][col]), Al + goff);   \
    }                                                                          \
    CP_COMMIT();                                                               \
} while (0)

    float4 vk[2][2];   // [pair][k, k+1]
#define LOAD_B(k0_) do {                                                       \
    _Pragma("unroll")                                                          \
    for (int p = 0; p < 2; ++p) {                                              \
        const float* gB = Bn + (size_t)((k0_) + b_kp + p * 32) * HW + p0 + b_px; \
        vk[p][0] = *(const float4*)gB;                                         \
        vk[p][1] = *(const float4*)(gB + HW);                                  \
    }                                                                          \
} while (0)

#define STORE_B() do {                                                         \
    _Pragma("unroll")                                                          \
    for (int p = 0; p < 2; ++p) {                                              \
        int kk = b_kp + p * 32;                                                \
        float a0[4] = {vk[p][0].x, vk[p][0].y, vk[p][0].z, vk[p][0].w};        \
        float a1[4] = {vk[p][1].x, vk[p][1].y, vk[p][1].z, vk[p][1].w};        \
        _Pragma("unroll")                                                      \
        for (int j = 0; j < 4; ++j) {                                          \
            uint32_t hi, lo;                                                   \
            split2(a0[j], a1[j], hi, lo);                                      \
            *(uint32_t*)&Bs_h[b_px + j][kk] = hi;                              \
            *(uint32_t*)&Bs_l[b_px + j][kk] = lo;                              \
        }                                                                      \
    }                                                                          \
} while (0)

    // prologue
    STAGE_A(0, 0);
    LOAD_B(0);

    for (int kc = 0; kc < KC; ++kc) {
        const int s = kc & 1;
        __syncthreads();            // prev MMA done: Bs free, stage s free of readers
        STORE_B();                  // regs hold chunk kc
        if (kc + 1 < KC) {
            STAGE_A(s ^ 1, (kc + 1) << 6);
            LOAD_B((kc + 1) << 6);
            CP_WAIT1();             // A(kc) complete (committed last iteration)
        } else {
            CP_WAIT0();
        }
        __syncthreads();

        tile_t ash = (tile_t)(gsm + s * G_STAGE);
        tile_t asl = (tile_t)(gsm + s * G_STAGE + G_AS_BYTES);
#pragma unroll
        for (int ks = 0; ks < 64; ks += 16) {
            uint32_t bf_hi[2][2], bf_lo[2][2];
#pragma unroll
            for (int nf = 0; nf < 2; ++nf) {
                int nb = warp_n * 16 + nf * 8;
                ldsm_x2(bf_hi[nf], b_addr(Bs_h, nb, ks, lid));
                ldsm_x2(bf_lo[nf], b_addr(Bs_l, nb, ks, lid));
            }
#pragma unroll
            for (int mf = 0; mf < 4; ++mf) {
                int mb = warp_m * 64 + mf * 16;
                uint32_t ah[4], al[4];
                ldsm_x4(ah, a_addr(ash, mb, ks, lid));
                ldsm_x4(al, a_addr(asl, mb, ks, lid));
#pragma unroll
                for (int nf = 0; nf < 2; ++nf) {
                    mma16816(acc[mf][nf], ah, bf_hi[nf]);
                    mma16816(acc[mf][nf], ah, bf_lo[nf]);
                    mma16816(acc[mf][nf], al, bf_hi[nf]);
                }
            }
        }
    }

#pragma unroll
    for (int mf = 0; mf < 4; ++mf) {
#pragma unroll
        for (int nf = 0; nf < 2; ++nf) {
            int m  = m0 + warp_m * 64 + mf * 16 + q;
            int px = p0 + warp_n * 16 + nf * 8 + 2 * r;
#pragma unroll
            for (int half = 0; half < 2; ++half) {
                int mm = m + half * 8;
                float c0 = acc[mf][nf][half * 2 + 0];
                float c1 = acc[mf][nf][half * 2 + 1];
                float bb = bias[mm];
                size_t base = ((size_t)n * M + mm) * HW + px;
                if (resid) {
                    float2 rv = *(const float2*)(resid + base);
                    c0 += rv.x;
                    c1 += rv.y;
                }
                float2 o;
                o.x = fmaxf(c0 + bb, 0.f);
                o.y = fmaxf(c1 + bb, 0.f);
                *(float2*)(C + base) = o;
            }
        }
    }
}

// ---------------------------------------------------------------------------
// Offset conv: 3x3 SAME, CB=256 -> 18 ch. 32 px/block (R9 version).
// ---------------------------------------------------------------------------
__global__ __launch_bounds__(256) void offset_conv_kernel(
        const float* __restrict__ w_off, const float* __restrict__ b_off) {
    __shared__ float red[8][32][18];
    const int n  = blockIdx.y;
    const int p0 = blockIdx.x * 32;
    const int tid = threadIdx.x;
    const int g  = tid >> 5;
    const int lx = tid & 31;

    float acc[18];
#pragma unroll
    for (int oc = 0; oc < 18; ++oc) acc[oc] = 0.f;

    const int p = p0 + lx;
    const int h = p / Ww, w = p % Ww;

    for (int ci = g; ci < CB; ci += 8) {
        const float* rb = g_r + ((size_t)n * CB + ci) * HW;
        float v[9];
#pragma unroll
        for (int t = 0; t < 9; ++t) {
            int y = h + t / 3 - 1;
            int x = w + t % 3 - 1;
            v[t] = (y >= 0 && y < Hh && x >= 0 && x < Ww) ? __ldg(rb + y * Ww + x) : 0.f;
        }
        const float* wb = w_off + ci * 9;
#pragma unroll
        for (int oc = 0; oc < 18; ++oc) {
#pragma unroll
            for (int t = 0; t < 9; ++t)
                acc[oc] += __ldg(wb + oc * (CB * 9) + t) * v[t];
        }
    }

#pragma unroll
    for (int oc = 0; oc < 18; ++oc)
        red[g][lx][oc] = acc[oc];
    __syncthreads();

    for (int i = tid; i < 32 * 18; i += 256) {
        int ps = i / 18, oc = i % 18;
        float s = b_off[oc];
#pragma unroll
        for (int g2 = 0; g2 < 8; ++g2) s += red[g2][ps][oc];
        g_off[((size_t)n * 18 + oc) * HW + p0 + ps] = s;
    }
}

// ===========================================================================
// Deformable 3x3 conv on tensor cores (R6-proven version, unchanged).
// ===========================================================================
#define DPITCH 72
#define DSM_AS_H 0
#define DSM_AS_L 18432
#define DSM_BS_H 36864
#define DSM_BS_L 46080
#define DSM_BYTES 55296

__global__ __launch_bounds__(256, 2) void deform_mma_kernel(const float* __restrict__ b2) {
    extern __shared__ char dsm[];
    typedef __nv_bfloat16 (*tile_t)[DPITCH];
    tile_t As_h = (tile_t)(dsm + DSM_AS_H);
    tile_t As_l = (tile_t)(dsm + DSM_AS_L);
    tile_t Bs_h = (tile_t)(dsm + DSM_BS_H);
    tile_t Bs_l = (tile_t)(dsm + DSM_BS_L);

    const int pb = blockIdx.x * 64;
    const int m0 = blockIdx.y * 128;
    const int n  = blockIdx.z;
    const int tid = threadIdx.x;
    const int wid = tid >> 5;
    const int lid = tid & 31;
    const int q = lid >> 2;
    const int r = lid & 3;
    const int wm = wid & 3;
    const int wn = wid >> 2;

    const int gpx = tid & 63;
    const int gg  = tid >> 6;
    const int gcl = gg * 16;

    const float* fbase = g_r + (size_t)n * CB * HW;
    const float* offb  = g_off + (size_t)n * 18 * HW + pb + gpx;
    const int gh = (pb + gpx) / Ww;
    const int gw = (pb + gpx) % Ww;

    float acc[2][4][4] = {};

    int   idx0, idx1, idx2, idx3;
    float wt0, wt1, wt2, wt3;
#define BILIN(tap_) do {                                                       \
    float dy = offb[(size_t)((tap_) * 2 + 0) * HW];                            \
    float dx = offb[(size_t)((tap_) * 2 + 1) * HW];                            \
    float ys = (float)(gh + (tap_) / 3 - 1) + dy;                              \
    float xs = (float)(gw + (tap_) % 3 - 1) + dx;                              \
    float y0f = floorf(ys), x0f = floorf(xs);                                  \
    float wy1 = ys - y0f, wy0 = 1.f - wy1;                                     \
    float wx1 = xs - x0f, wx0 = 1.f - wx1;                                     \
    int y0 = (int)y0f, x0 = (int)x0f;                                          \
    int y1 = y0 + 1, x1 = x0 + 1;                                              \
    bool vy0 = (y0 >= 0) && (y0 < Hh);                                         \
    bool vy1 = (y1 >= 0) && (y1 < Hh);                                         \
    bool vx0 = (x0 >= 0) && (x0 < Ww);                                         \
    bool vx1 = (x1 >= 0) && (x1 < Ww);                                         \
    int yc0 = min(max(y0, 0), Hh - 1), yc1 = min(max(y1, 0), Hh - 1);          \
    int xc0 = min(max(x0, 0), Ww - 1), xc1 = min(max(x1, 0), Ww - 1);          \
    idx0 = yc0 * Ww + xc0;  wt0 = (vy0 && vx0) ? wy0 * wx0 : 0.f;              \
    idx1 = yc0 * Ww + xc1;  wt1 = (vy0 && vx1) ? wy0 * wx1 : 0.f;              \
    idx2 = yc1 * Ww + xc0;  wt2 = (vy1 && vx0) ? wy1 * wx0 : 0.f;              \
    idx3 = yc1 * Ww + xc1;  wt3 = (vy1 && vx1) ? wy1 * wx1 : 0.f;              \
} while (0)

    float v[16];
#define GATHER(c0_) do {                                                       \
    _Pragma("unroll")                                                          \
    for (int j = 0; j < 16; ++j) {                                             \
        const float* f = fbase + (size_t)((c0_) + gcl + j) * HW;               \
        v[j] = wt0 * __ldg(f + idx0) + wt1 * __ldg(f + idx1)                   \
             + wt2 * __ldg(f + idx2) + wt3 * __ldg(f + idx3);                  \
    }                                                                          \
} while (0)

    BILIN(0);
    GATHER(0);
    int tap_cur = 0;

    for (int ch = 0; ch < 36; ++ch) {
        const int tap = ch >> 2;
        const int k0  = tap * 256 + (ch & 3) * 64;
        __syncthreads();

        {
            uint4 h0, h1, l0, l1;
            split2(v[0],  v[1],  h0.x, l0.x);
            split2(v[2],  v[3],  h0.y, l0.y);
            split2(v[4],  v[5],  h0.z, l0.z);
            split2(v[6],  v[7],  h0.w, l0.w);
            split2(v[8],  v[9],  h1.x, l1.x);
            split2(v[10], v[11], h1.y, l1.y);
            split2(v[12], v[13], h1.z, l1.z);
            split2(v[14], v[15], h1.w, l1.w);
            *(uint4*)&Bs_h[gpx][gcl]     = h0;
            *(uint4*)&Bs_h[gpx][gcl + 8] = h1;
            *(uint4*)&Bs_l[gpx][gcl]     = l0;
            *(uint4*)&Bs_l[gpx][gcl + 8] = l1;
        }
#pragma unroll
        for (int pass = 0; pass < 4; ++pass) {
            int id   = tid + pass * 256;
            int row  = id >> 3;
            int col  = (id & 7) * 8;
            size_t goff = (size_t)(m0 + row) * KD + k0 + col;
            cp16((uint32_t)__cvta_generic_to_shared(&As_h[row][col]), g_w2h + goff);
            cp16((uint32_t)__cvta_generic_to_shared(&As_l[row][col]), g_w2l + goff);
        }
        CP_COMMIT();

        if (ch + 1 < 36) {
            int ntap = (ch + 1) >> 2;
            if (ntap != tap_cur) {
                BILIN(ntap);
                tap_cur = ntap;
            }
            GATHER(((ch + 1) & 3) * 64);
        }

        CP_WAIT0();
        __syncthreads();

#pragma unroll
        for (int ks = 0; ks < 64; ks += 16) {
            uint32_t bh[4][2], bl[4][2];
#pragma unroll
            for (int nf = 0; nf < 4; ++nf) {
                int nb = wn * 32 + nf * 8;
                ldsm_x2(bh[nf], b_addr(Bs_h, nb, ks, lid));
                ldsm_x2(bl[nf], b_addr(Bs_l, nb, ks, lid));
            }
#pragma unroll
            for (int mf = 0; mf < 2; ++mf) {
                int mb = wm * 32 + mf * 16;
                uint32_t ah[4], al[4];
                ldsm_x4(ah, a_addr(As_h, mb, ks, lid));
                ldsm_x4(al, a_addr(As_l, mb, ks, lid));
#pragma unroll
                for (int nf = 0; nf < 4; ++nf) {
                    mma16816(acc[mf][nf], ah, bh[nf]);
                    mma16816(acc[mf][nf], ah, bl[nf]);
                    mma16816(acc[mf][nf], al, bh[nf]);
                }
            }
        }
    }

#pragma unroll
    for (int mf = 0; mf < 2; ++mf) {
#pragma unroll
        for (int half = 0; half < 2; ++half) {
            int o = m0 + wm * 32 + mf * 16 + q + half * 8;
            float bb = b2[o];
            float* orow = g_r2 + ((size_t)n * CB + o) * HW + pb;
#pragma unroll
            for (int nf = 0; nf < 4; ++nf) {
                int px = wn * 32 + nf * 8 + 2 * r;
                float2 ov;
                ov.x = fmaxf(acc[mf][nf][half * 2 + 0] + bb, 0.f);
                ov.y = fmaxf(acc[mf][nf][half * 2 + 1] + bb, 0.f);
                *(float2*)(orow + px) = ov;
            }
        }
    }
}

// ---------------------------------------------------------------------------
extern "C" void kernel_launch(void* const* d_in, const int* in_sizes, int n_in,
                              void* d_out, int out_size) {
    const float* x     = (const float*)d_in[0];
    const float* w1    = (const float*)d_in[1];
    const float* b1    = (const float*)d_in[2];
    const float* w_off = (const float*)d_in[3];
    const float* b_off = (const float*)d_in[4];
    const float* w2    = (const float*)d_in[5];
    const float* b2    = (const float*)d_in[6];
    const float* w3    = (const float*)d_in[7];
    const float* b3    = (const float*)d_in[8];
    float* out = (float*)d_out;

    float *r_ptr, *r2_ptr;
    cudaGetSymbolAddress((void**)&r_ptr, g_r);
    cudaGetSymbolAddress((void**)&r2_ptr, g_r2);
    __nv_bfloat16 *w1h, *w1l, *w3h, *w3l;
    cudaGetSymbolAddress((void**)&w1h, g_w1h);
    cudaGetSymbolAddress((void**)&w1l, g_w1l);
    cudaGetSymbolAddress((void**)&w3h, g_w3h);
    cudaGetSymbolAddress((void**)&w3l, g_w3l);

    cudaFuncSetAttribute(deform_mma_kernel,
                         cudaFuncAttributeMaxDynamicSharedMemorySize, DSM_BYTES);
    cudaFuncSetAttribute(gemm_tc_kernel,
                         cudaFuncAttributeMaxDynamicSharedMemorySize, GSM_BYTES);

    // weight preps
    prep_w2_kernel<<<(CB * KD + 255) / 256, 256>>>(w2);
    prep_w_kernel<<<(CB * CIN + 255) / 256, 256>>>(w1, w1h, w1l, CB * CIN);
    prep_w_kernel<<<(CIN * CB + 255) / 256, 256>>>(w3, w3h, w3l, CIN * CB);

    // conv1: 1024 -> 256, relu
    gemm_tc_kernel<<<dim3(HW / 64, CB / 128, Nn), 256, GSM_BYTES>>>(
        w1h, w1l, x, b1, nullptr, r_ptr, CB, CIN);

    // offset conv 3x3: 256 -> 18
    offset_conv_kernel<<<dim3(HW / 32, Nn), 256>>>(w_off, b_off);

    // deformable conv 3x3: 256 -> 256, relu
    deform_mma_kernel<<<dim3(HW / 64, 2, Nn), 256, DSM_BYTES>>>(b2);

    // conv3: 256 -> 1024 + x residual, relu
    gemm_tc_kernel<<<dim3(HW / 64, CIN / 128, Nn), 256, GSM_BYTES>>>(
        w3h, w3l, r2_ptr, b3, x, out, CIN, CB);
}

// round 11
// speedup vs baseline: 1.3717x; 1.0246x over previous
#include <cuda_runtime.h>
#include <cuda_bf16.h>
#include <math.h>
#include <stdint.h>

#define Nn   4
#define CIN  1024
#define CB   256
#define Hh   56
#define Ww   56
#define HW   3136
#define KT   9
#define KD   (CB * KT)   // 2304

// Scratch (device globals: allocation-free rule)
__device__ float g_r  [Nn * CB * HW];     // conv1 output (relu)
__device__ float g_off[Nn * 2 * KT * HW]; // offset conv output
__device__ float g_r2 [Nn * CB * HW];     // deform conv output (relu)
__device__ __nv_bfloat16 g_w2h[CB * KD];  // w2 split hi, [o][tap*256+c]
__device__ __nv_bfloat16 g_w2l[CB * KD];  // w2 split lo
__device__ __nv_bfloat16 g_w1h[CB * CIN]; // w1 split hi [256][1024]
__device__ __nv_bfloat16 g_w1l[CB * CIN];
__device__ __nv_bfloat16 g_w3h[CIN * CB]; // w3 split hi [1024][256]
__device__ __nv_bfloat16 g_w3l[CIN * CB];

// ---------------------------------------------------------------------------
// helpers
// ---------------------------------------------------------------------------
__device__ __forceinline__ void split2(float x, float y, uint32_t& hi, uint32_t& lo) {
    __nv_bfloat16 xh = __float2bfloat16(x);
    __nv_bfloat16 yh = __float2bfloat16(y);
    __nv_bfloat16 xl = __float2bfloat16(x - __bfloat162float(xh));
    __nv_bfloat16 yl = __float2bfloat16(y - __bfloat162float(yh));
    hi = ((uint32_t)__bfloat16_as_ushort(yh) << 16) | __bfloat16_as_ushort(xh);
    lo = ((uint32_t)__bfloat16_as_ushort(yl) << 16) | __bfloat16_as_ushort(xl);
}

__device__ __forceinline__ void mma16816(float* c, const uint32_t* a, const uint32_t* b) {
    asm volatile(
        "mma.sync.aligned.m16n8k16.row.col.f32.bf16.bf16.f32 "
        "{%0,%1,%2,%3}, {%4,%5,%6,%7}, {%8,%9}, {%0,%1,%2,%3};"
        : "+f"(c[0]), "+f"(c[1]), "+f"(c[2]), "+f"(c[3])
        : "r"(a[0]), "r"(a[1]), "r"(a[2]), "r"(a[3]), "r"(b[0]), "r"(b[1]));
}

__device__ __forceinline__ void ldsm_x4(uint32_t* r, uint32_t addr) {
    asm volatile("ldmatrix.sync.aligned.m8n8.x4.shared.b16 {%0,%1,%2,%3}, [%4];"
                 : "=r"(r[0]), "=r"(r[1]), "=r"(r[2]), "=r"(r[3]) : "r"(addr));
}
__device__ __forceinline__ void ldsm_x2(uint32_t* r, uint32_t addr) {
    asm volatile("ldmatrix.sync.aligned.m8n8.x2.shared.b16 {%0,%1}, [%2];"
                 : "=r"(r[0]), "=r"(r[1]) : "r"(addr));
}
template <int P>
__device__ __forceinline__ uint32_t a_addr(const __nv_bfloat16 (*S)[P], int mb, int ks, int ln) {
    int row = mb + (ln & 7) + ((ln >> 3) & 1) * 8;
    int col = ks + (ln >> 4) * 8;
    return (uint32_t)__cvta_generic_to_shared(&S[row][col]);
}
template <int P>
__device__ __forceinline__ uint32_t b_addr(const __nv_bfloat16 (*S)[P], int nb, int ks, int ln) {
    int l = ln & 15;
    int row = nb + (l & 7);
    int col = ks + ((l >> 3) & 1) * 8;
    return (uint32_t)__cvta_generic_to_shared(&S[row][col]);
}
__device__ __forceinline__ void cp16(uint32_t saddr, const void* g) {
    asm volatile("cp.async.ca.shared.global [%0], [%1], 16;"
                 :: "r"(saddr), "l"(g) : "memory");
}
#define CP_COMMIT() asm volatile("cp.async.commit_group;" ::: "memory")
#define CP_WAIT0()  asm volatile("cp.async.wait_group 0;" ::: "memory")
#define CP_WAIT1()  asm volatile("cp.async.wait_group 1;" ::: "memory")

// ---------------------------------------------------------------------------
// weight prep: fp32 -> bf16 hi/lo
// ---------------------------------------------------------------------------
__global__ void prep_w2_kernel(const float* __restrict__ w2) {
    int i = blockIdx.x * 256 + threadIdx.x;
    if (i < CB * KD) {
        int o = i / KD;
        int k = i % KD;
        int tap = k >> 8;
        int c   = k & 255;
        float v = w2[(o * CB + c) * KT + tap];
        __nv_bfloat16 h = __float2bfloat16(v);
        g_w2h[i] = h;
        g_w2l[i] = __float2bfloat16(v - __bfloat162float(h));
    }
}
__global__ void prep_w_kernel(const float* __restrict__ w,
                              __nv_bfloat16* __restrict__ oh,
                              __nv_bfloat16* __restrict__ ol, int total) {
    int i = blockIdx.x * 256 + threadIdx.x;
    if (i < total) {
        float v = w[i];
        __nv_bfloat16 h = __float2bfloat16(v);
        oh[i] = h;
        ol[i] = __float2bfloat16(v - __bfloat162float(h));
    }
}

// ===========================================================================
// Tensor-core GEMM for 1x1 convs. BK=64, pre-split A via cp.async 2-stage.
// Warp tiling 4m x 2n (warp = 32 rows x 32 px) to cut redundant A ldmatrix.
// ===========================================================================
#define GKP 72
#define G_AS_BYTES (128 * GKP * 2)          // 18432 per h/l tile
#define G_STAGE    (2 * G_AS_BYTES)         // 36864 per stage (h+l)
#define G_B_OFF    (2 * G_STAGE)            // 73728
#define G_BS_BYTES (64 * GKP * 2)           // 9216
#define GSM_BYTES  (G_B_OFF + 2 * G_BS_BYTES)  // 92160

__global__ __launch_bounds__(256) void gemm_tc_kernel(
        const __nv_bfloat16* __restrict__ Ah,
        const __nv_bfloat16* __restrict__ Al,
        const float* __restrict__ Bx,
        const float* __restrict__ bias, const float* __restrict__ resid,
        float* __restrict__ C, int M, int Kd) {
    extern __shared__ char gsm[];
    typedef __nv_bfloat16 (*tile_t)[GKP];
    tile_t Bs_h = (tile_t)(gsm + G_B_OFF);
    tile_t Bs_l = (tile_t)(gsm + G_B_OFF + G_BS_BYTES);

    const int n  = blockIdx.z;
    const int m0 = blockIdx.y * 128;
    const int p0 = blockIdx.x * 64;
    const int tid = threadIdx.x;
    const int wid = tid >> 5;
    const int lid = tid & 31;
    const int q = lid >> 2;
    const int r = lid & 3;
    const int wm = wid & 3;     // 4 m-warps x 32 rows
    const int wn = wid >> 2;    // 2 n-warps x 32 px
    const float* Bn = Bx + (size_t)n * Kd * HW;

    // B-load role: px-major coalesced
    const int b_px = (tid & 15) * 4;     // 0..60
    const int b_kp = (tid >> 4) * 2;     // k-pair base 0..30 (+32 for second)

    float acc[2][4][4] = {};
    const int KC = Kd >> 6;

#define STAGE_A(s_, k0_) do {                                                  \
    tile_t _ah = (tile_t)(gsm + (s_) * G_STAGE);                               \
    tile_t _al = (tile_t)(gsm + (s_) * G_STAGE + G_AS_BYTES);                  \
    _Pragma("unroll")                                                          \
    for (int pass = 0; pass < 4; ++pass) {                                     \
        int id  = tid + pass * 256;                                            \
        int row = id >> 3;                                                     \
        int col = (id & 7) * 8;                                                \
        size_t goff = (size_t)(m0 + row) * Kd + (k0_) + col;                   \
        cp16((uint32_t)__cvta_generic_to_shared(&_ah[row][col]), Ah + goff);   \
        cp16((uint32_t)__cvta_generic_to_shared(&_al[row][col]), Al + goff);   \
    }                                                                          \
    CP_COMMIT();                                                               \
} while (0)

    float4 vk[2][2];   // [pair][k, k+1]
#define LOAD_B(k0_) do {                                                       \
    _Pragma("unroll")                                                          \
    for (int p = 0; p < 2; ++p) {                                              \
        const float* gB = Bn + (size_t)((k0_) + b_kp + p * 32) * HW + p0 + b_px; \
        vk[p][0] = *(const float4*)gB;                                         \
        vk[p][1] = *(const float4*)(gB + HW);                                  \
    }                                                                          \
} while (0)

#define STORE_B() do {                                                         \
    _Pragma("unroll")                                                          \
    for (int p = 0; p < 2; ++p) {                                              \
        int kk = b_kp + p * 32;                                                \
        float a0[4] = {vk[p][0].x, vk[p][0].y, vk[p][0].z, vk[p][0].w};        \
        float a1[4] = {vk[p][1].x, vk[p][1].y, vk[p][1].z, vk[p][1].w};        \
        _Pragma("unroll")                                                      \
        for (int j = 0; j < 4; ++j) {                                          \
            uint32_t hi, lo;                                                   \
            split2(a0[j], a1[j], hi, lo);                                      \
            *(uint32_t*)&Bs_h[b_px + j][kk] = hi;                              \
            *(uint32_t*)&Bs_l[b_px + j][kk] = lo;                              \
        }                                                                      \
    }                                                                          \
} while (0)

    // prologue
    STAGE_A(0, 0);
    LOAD_B(0);

    for (int kc = 0; kc < KC; ++kc) {
        const int s = kc & 1;
        __syncthreads();            // prev MMA done: Bs free, stage s free
        STORE_B();                  // regs hold chunk kc
        if (kc + 1 < KC) {
            STAGE_A(s ^ 1, (kc + 1) << 6);
            LOAD_B((kc + 1) << 6);
            CP_WAIT1();             // A(kc) complete (committed last iteration)
        } else {
            CP_WAIT0();
        }
        __syncthreads();

        tile_t ash = (tile_t)(gsm + s * G_STAGE);
        tile_t asl = (tile_t)(gsm + s * G_STAGE + G_AS_BYTES);
#pragma unroll
        for (int ks = 0; ks < 64; ks += 16) {
            uint32_t bh[4][2], bl[4][2];
#pragma unroll
            for (int nf = 0; nf < 4; ++nf) {
                int nb = wn * 32 + nf * 8;
                ldsm_x2(bh[nf], b_addr(Bs_h, nb, ks, lid));
                ldsm_x2(bl[nf], b_addr(Bs_l, nb, ks, lid));
            }
#pragma unroll
            for (int mf = 0; mf < 2; ++mf) {
                int mb = wm * 32 + mf * 16;
                uint32_t ah[4], al[4];
                ldsm_x4(ah, a_addr(ash, mb, ks, lid));
                ldsm_x4(al, a_addr(asl, mb, ks, lid));
#pragma unroll
                for (int nf = 0; nf < 4; ++nf) {
                    mma16816(acc[mf][nf], ah, bh[nf]);
                    mma16816(acc[mf][nf], ah, bl[nf]);
                    mma16816(acc[mf][nf], al, bh[nf]);
                }
            }
        }
    }

    // epilogue
#pragma unroll
    for (int mf = 0; mf < 2; ++mf) {
#pragma unroll
        for (int half = 0; half < 2; ++half) {
            int mm = m0 + wm * 32 + mf * 16 + q + half * 8;
            float bb = bias[mm];
#pragma unroll
            for (int nf = 0; nf < 4; ++nf) {
                int px = p0 + wn * 32 + nf * 8 + 2 * r;
                float c0 = acc[mf][nf][half * 2 + 0];
                float c1 = acc[mf][nf][half * 2 + 1];
                size_t base = ((size_t)n * M + mm) * HW + px;
                if (resid) {
                    float2 rv = *(const float2*)(resid + base);
                    c0 += rv.x;
                    c1 += rv.y;
                }
                float2 o;
                o.x = fmaxf(c0 + bb, 0.f);
                o.y = fmaxf(c1 + bb, 0.f);
                *(float2*)(C + base) = o;
            }
        }
    }
}

// ---------------------------------------------------------------------------
// Offset conv: 3x3 SAME, CB=256 -> 18 ch. 32 px/block (R9 version).
// ---------------------------------------------------------------------------
__global__ __launch_bounds__(256) void offset_conv_kernel(
        const float* __restrict__ w_off, const float* __restrict__ b_off) {
    __shared__ float red[8][32][18];
    const int n  = blockIdx.y;
    const int p0 = blockIdx.x * 32;
    const int tid = threadIdx.x;
    const int g  = tid >> 5;
    const int lx = tid & 31;

    float acc[18];
#pragma unroll
    for (int oc = 0; oc < 18; ++oc) acc[oc] = 0.f;

    const int p = p0 + lx;
    const int h = p / Ww, w = p % Ww;

    for (int ci = g; ci < CB; ci += 8) {
        const float* rb = g_r + ((size_t)n * CB + ci) * HW;
        float v[9];
#pragma unroll
        for (int t = 0; t < 9; ++t) {
            int y = h + t / 3 - 1;
            int x = w + t % 3 - 1;
            v[t] = (y >= 0 && y < Hh && x >= 0 && x < Ww) ? __ldg(rb + y * Ww + x) : 0.f;
        }
        const float* wb = w_off + ci * 9;
#pragma unroll
        for (int oc = 0; oc < 18; ++oc) {
#pragma unroll
            for (int t = 0; t < 9; ++t)
                acc[oc] += __ldg(wb + oc * (CB * 9) + t) * v[t];
        }
    }

#pragma unroll
    for (int oc = 0; oc < 18; ++oc)
        red[g][lx][oc] = acc[oc];
    __syncthreads();

    for (int i = tid; i < 32 * 18; i += 256) {
        int ps = i / 18, oc = i % 18;
        float s = b_off[oc];
#pragma unroll
        for (int g2 = 0; g2 < 8; ++g2) s += red[g2][ps][oc];
        g_off[((size_t)n * 18 + oc) * HW + p0 + ps] = s;
    }
}

// ===========================================================================
// Deformable 3x3 conv on tensor cores (R6/R9-proven; STAGE_W issued before
// STORE_B so the cp.async latency cover starts earlier).
// ===========================================================================
#define DPITCH 72
#define DSM_AS_H 0
#define DSM_AS_L 18432
#define DSM_BS_H 36864
#define DSM_BS_L 46080
#define DSM_BYTES 55296

__global__ __launch_bounds__(256, 2) void deform_mma_kernel(const float* __restrict__ b2) {
    extern __shared__ char dsm[];
    typedef __nv_bfloat16 (*tile_t)[DPITCH];
    tile_t As_h = (tile_t)(dsm + DSM_AS_H);
    tile_t As_l = (tile_t)(dsm + DSM_AS_L);
    tile_t Bs_h = (tile_t)(dsm + DSM_BS_H);
    tile_t Bs_l = (tile_t)(dsm + DSM_BS_L);

    const int pb = blockIdx.x * 64;
    const int m0 = blockIdx.y * 128;
    const int n  = blockIdx.z;
    const int tid = threadIdx.x;
    const int wid = tid >> 5;
    const int lid = tid & 31;
    const int q = lid >> 2;
    const int r = lid & 3;
    const int wm = wid & 3;
    const int wn = wid >> 2;

    const int gpx = tid & 63;
    const int gg  = tid >> 6;
    const int gcl = gg * 16;

    const float* fbase = g_r + (size_t)n * CB * HW;
    const float* offb  = g_off + (size_t)n * 18 * HW + pb + gpx;
    const int gh = (pb + gpx) / Ww;
    const int gw = (pb + gpx) % Ww;

    float acc[2][4][4] = {};

    int   idx0, idx1, idx2, idx3;
    float wt0, wt1, wt2, wt3;
#define BILIN(tap_) do {                                                       \
    float dy = offb[(size_t)((tap_) * 2 + 0) * HW];                            \
    float dx = offb[(size_t)((tap_) * 2 + 1) * HW];                            \
    float ys = (float)(gh + (tap_) / 3 - 1) + dy;                              \
    float xs = (float)(gw + (tap_) % 3 - 1) + dx;                              \
    float y0f = floorf(ys), x0f = floorf(xs);                                  \
    float wy1 = ys - y0f, wy0 = 1.f - wy1;                                     \
    float wx1 = xs - x0f, wx0 = 1.f - wx1;                                     \
    int y0 = (int)y0f, x0 = (int)x0f;                                          \
    int y1 = y0 + 1, x1 = x0 + 1;                                              \
    bool vy0 = (y0 >= 0) && (y0 < Hh);                                         \
    bool vy1 = (y1 >= 0) && (y1 < Hh);                                         \
    bool vx0 = (x0 >= 0) && (x0 < Ww);                                         \
    bool vx1 = (x1 >= 0) && (x1 < Ww);                                         \
    int yc0 = min(max(y0, 0), Hh - 1), yc1 = min(max(y1, 0), Hh - 1);          \
    int xc0 = min(max(x0, 0), Ww - 1), xc1 = min(max(x1, 0), Ww - 1);          \
    idx0 = yc0 * Ww + xc0;  wt0 = (vy0 && vx0) ? wy0 * wx0 : 0.f;              \
    idx1 = yc0 * Ww + xc1;  wt1 = (vy0 && vx1) ? wy0 * wx1 : 0.f;              \
    idx2 = yc1 * Ww + xc0;  wt2 = (vy1 && vx0) ? wy1 * wx0 : 0.f;              \
    idx3 = yc1 * Ww + xc1;  wt3 = (vy1 && vx1) ? wy1 * wx1 : 0.f;              \
} while (0)

    float v[16];
#define GATHER(c0_) do {                                                       \
    _Pragma("unroll")                                                          \
    for (int j = 0; j < 16; ++j) {                                             \
        const float* f = fbase + (size_t)((c0_) + gcl + j) * HW;               \
        v[j] = wt0 * __ldg(f + idx0) + wt1 * __ldg(f + idx1)                   \
             + wt2 * __ldg(f + idx2) + wt3 * __ldg(f + idx3);                  \
    }                                                                          \
} while (0)

    BILIN(0);
    GATHER(0);
    int tap_cur = 0;

    for (int ch = 0; ch < 36; ++ch) {
        const int tap = ch >> 2;
        const int k0  = tap * 256 + (ch & 3) * 64;
        __syncthreads();

        // stage weights via cp.async FIRST (latency cover starts now)
#pragma unroll
        for (int pass = 0; pass < 4; ++pass) {
            int id   = tid + pass * 256;
            int row  = id >> 3;
            int col  = (id & 7) * 8;
            size_t goff = (size_t)(m0 + row) * KD + k0 + col;
            cp16((uint32_t)__cvta_generic_to_shared(&As_h[row][col]), g_w2h + goff);
            cp16((uint32_t)__cvta_generic_to_shared(&As_l[row][col]), g_w2l + goff);
        }
        CP_COMMIT();

        // store gathered values -> Bs (split bf16 hi/lo)
        {
            uint4 h0, h1, l0, l1;
            split2(v[0],  v[1],  h0.x, l0.x);
            split2(v[2],  v[3],  h0.y, l0.y);
            split2(v[4],  v[5],  h0.z, l0.z);
            split2(v[6],  v[7],  h0.w, l0.w);
            split2(v[8],  v[9],  h1.x, l1.x);
            split2(v[10], v[11], h1.y, l1.y);
            split2(v[12], v[13], h1.z, l1.z);
            split2(v[14], v[15], h1.w, l1.w);
            *(uint4*)&Bs_h[gpx][gcl]     = h0;
            *(uint4*)&Bs_h[gpx][gcl + 8] = h1;
            *(uint4*)&Bs_l[gpx][gcl]     = l0;
            *(uint4*)&Bs_l[gpx][gcl + 8] = l1;
        }

        if (ch + 1 < 36) {
            int ntap = (ch + 1) >> 2;
            if (ntap != tap_cur) {
                BILIN(ntap);
                tap_cur = ntap;
            }
            GATHER(((ch + 1) & 3) * 64);
        }

        CP_WAIT0();
        __syncthreads();

#pragma unroll
        for (int ks = 0; ks < 64; ks += 16) {
            uint32_t bh[4][2], bl[4][2];
#pragma unroll
            for (int nf = 0; nf < 4; ++nf) {
                int nb = wn * 32 + nf * 8;
                ldsm_x2(bh[nf], b_addr(Bs_h, nb, ks, lid));
                ldsm_x2(bl[nf], b_addr(Bs_l, nb, ks, lid));
            }
#pragma unroll
            for (int mf = 0; mf < 2; ++mf) {
                int mb = wm * 32 + mf * 16;
                uint32_t ah[4], al[4];
                ldsm_x4(ah, a_addr(As_h, mb, ks, lid));
                ldsm_x4(al, a_addr(As_l, mb, ks, lid));
#pragma unroll
                for (int nf = 0; nf < 4; ++nf) {
                    mma16816(acc[mf][nf], ah, bh[nf]);
                    mma16816(acc[mf][nf], ah, bl[nf]);
                    mma16816(acc[mf][nf], al, bh[nf]);
                }
            }
        }
    }

#pragma unroll
    for (int mf = 0; mf < 2; ++mf) {
#pragma unroll
        for (int half = 0; half < 2; ++half) {
            int o = m0 + wm * 32 + mf * 16 + q + half * 8;
            float bb = b2[o];
            float* orow = g_r2 + ((size_t)n * CB + o) * HW + pb;
#pragma unroll
            for (int nf = 0; nf < 4; ++nf) {
                int px = wn * 32 + nf * 8 + 2 * r;
                float2 ov;
                ov.x = fmaxf(acc[mf][nf][half * 2 + 0] + bb, 0.f);
                ov.y = fmaxf(acc[mf][nf][half * 2 + 1] + bb, 0.f);
                *(float2*)(orow + px) = ov;
            }
        }
    }
}

// ---------------------------------------------------------------------------
extern "C" void kernel_launch(void* const* d_in, const int* in_sizes, int n_in,
                              void* d_out, int out_size) {
    const float* x     = (const float*)d_in[0];
    const float* w1    = (const float*)d_in[1];
    const float* b1    = (const float*)d_in[2];
    const float* w_off = (const float*)d_in[3];
    const float* b_off = (const float*)d_in[4];
    const float* w2    = (const float*)d_in[5];
    const float* b2    = (const float*)d_in[6];
    const float* w3    = (const float*)d_in[7];
    const float* b3    = (const float*)d_in[8];
    float* out = (float*)d_out;

    float *r_ptr, *r2_ptr;
    cudaGetSymbolAddress((void**)&r_ptr, g_r);
    cudaGetSymbolAddress((void**)&r2_ptr, g_r2);
    __nv_bfloat16 *w1h, *w1l, *w3h, *w3l;
    cudaGetSymbolAddress((void**)&w1h, g_w1h);
    cudaGetSymbolAddress((void**)&w1l, g_w1l);
    cudaGetSymbolAddress((void**)&w3h, g_w3h);
    cudaGetSymbolAddress((void**)&w3l, g_w3l);

    cudaFuncSetAttribute(deform_mma_kernel,
                         cudaFuncAttributeMaxDynamicSharedMemorySize, DSM_BYTES);
    cudaFuncSetAttribute(gemm_tc_kernel,
                         cudaFuncAttributeMaxDynamicSharedMemorySize, GSM_BYTES);

    // weight preps
    prep_w2_kernel<<<(CB * KD + 255) / 256, 256>>>(w2);
    prep_w_kernel<<<(CB * CIN + 255) / 256, 256>>>(w1, w1h, w1l, CB * CIN);
    prep_w_kernel<<<(CIN * CB + 255) / 256, 256>>>(w3, w3h, w3l, CIN * CB);

    // conv1: 1024 -> 256, relu
    gemm_tc_kernel<<<dim3(HW / 64, CB / 128, Nn), 256, GSM_BYTES>>>(
        w1h, w1l, x, b1, nullptr, r_ptr, CB, CIN);

    // offset conv 3x3: 256 -> 18
    offset_conv_kernel<<<dim3(HW / 32, Nn), 256>>>(w_off, b_off);

    // deformable conv 3x3: 256 -> 256, relu
    deform_mma_kernel<<<dim3(HW / 64, 2, Nn), 256, DSM_BYTES>>>(b2);

    // conv3: 256 -> 1024 + x residual, relu
    gemm_tc_kernel<<<dim3(HW / 64, CIN / 128, Nn), 256, GSM_BYTES>>>(
        w3h, w3l, r2_ptr, b3, x, out, CIN, CB);
}